// round 3
// baseline (speedup 1.0000x reference)
#include <cuda_runtime.h>
#include <cstddef>

#define HIDDEN   128
#define INSZ     64
#define NACT     16
#define BATCH    65536
#define TILE_B   128
#define THREADS  128

#define XS_STRIDE 68    // 64 + 4 pad: conflict-free vec4 LDS
#define H0_STRIDE 132   // 128 + 4 pad

extern __shared__ float smem_buf[];

__device__ __forceinline__ float fsig(float z) {
    return __fdividef(1.0f, 1.0f + __expf(-z));
}
__device__ __forceinline__ float ftanh_(float z) {
    // tanh(z) = 2*sigmoid(2z) - 1  (accurate via __expf, ~1e-6 rel err)
    return 2.0f * fsig(2.0f * z) - 1.0f;
}
__device__ __forceinline__ float dot4(float4 a, float4 b, float acc) {
    acc = fmaf(a.x, b.x, acc);
    acc = fmaf(a.y, b.y, acc);
    acc = fmaf(a.z, b.z, acc);
    acc = fmaf(a.w, b.w, acc);
    return acc;
}

__global__ void __launch_bounds__(THREADS)
lstm_policy_fused(
    const float* __restrict__ x,
    const float* __restrict__ Wih0,
    const float* __restrict__ bih0, const float* __restrict__ bhh0,
    const float* __restrict__ Wih1,
    const float* __restrict__ bih1, const float* __restrict__ bhh1,
    const float* __restrict__ Wp,   const float* __restrict__ bp,
    const float* __restrict__ Wv,   const float* __restrict__ bv,
    float* __restrict__ out)
{
    float* xs  = smem_buf;                       // [TILE_B][XS_STRIDE]
    float* h0s = smem_buf + TILE_B * XS_STRIDE;  // [TILE_B][H0_STRIDE]

    const int tid = threadIdx.x;
    const int r0  = blockIdx.x * TILE_B;

    // ---- stage x tile (coalesced float4 global read) ----
    {
        const float4* xg = (const float4*)x;
        #pragma unroll
        for (int idx = tid; idx < TILE_B * (INSZ / 4); idx += THREADS) {
            int r = idx >> 4;        // row within tile
            int c = idx & 15;        // float4 column
            float4 v = xg[(size_t)(r0 + r) * (INSZ / 4) + c];
            *(float4*)&xs[r * XS_STRIDE + 4 * c] = v;
        }
    }
    __syncthreads();

    const float* xrow = &xs[tid * XS_STRIDE];
    float* hrow = &h0s[tid * H0_STRIDE];

    // ---------------- layer 0 ----------------
    // c=0, h=0  =>  gates = x @ Wih0^T + (bih0 + bhh0); f-gate unused.
    for (int j = 0; j < HIDDEN; ++j) {
        float ai = bih0[j]              + bhh0[j];
        float ag = bih0[2 * HIDDEN + j] + bhh0[2 * HIDDEN + j];
        float ao = bih0[3 * HIDDEN + j] + bhh0[3 * HIDDEN + j];

        const float4* wi = (const float4*)(Wih0 + (size_t)j * INSZ);
        const float4* wg = (const float4*)(Wih0 + (size_t)(2 * HIDDEN + j) * INSZ);
        const float4* wo = (const float4*)(Wih0 + (size_t)(3 * HIDDEN + j) * INSZ);

        #pragma unroll
        for (int k = 0; k < INSZ / 4; ++k) {
            float4 xv = *(const float4*)&xrow[4 * k];
            ai = dot4(xv, wi[k], ai);
            ag = dot4(xv, wg[k], ag);
            ao = dot4(xv, wo[k], ao);
        }

        float ig = fsig(ai);
        float gg = ftanh_(ag);
        float og = fsig(ao);
        float cc = ig * gg;                 // f*c term is zero
        hrow[j]  = og * ftanh_(cc);
    }
    // Each thread reads only the h0 row it wrote -> no __syncthreads needed.

    // ---------------- layer 1 + heads ----------------
    float pol[NACT];
    #pragma unroll
    for (int a = 0; a < NACT; ++a) pol[a] = 0.0f;
    float valacc = 0.0f;

    for (int j = 0; j < HIDDEN; ++j) {
        float ai = bih1[j]              + bhh1[j];
        float ag = bih1[2 * HIDDEN + j] + bhh1[2 * HIDDEN + j];
        float ao = bih1[3 * HIDDEN + j] + bhh1[3 * HIDDEN + j];

        const float4* wi = (const float4*)(Wih1 + (size_t)j * HIDDEN);
        const float4* wg = (const float4*)(Wih1 + (size_t)(2 * HIDDEN + j) * HIDDEN);
        const float4* wo = (const float4*)(Wih1 + (size_t)(3 * HIDDEN + j) * HIDDEN);

        #pragma unroll
        for (int k = 0; k < HIDDEN / 4; ++k) {
            float4 xv = *(const float4*)&hrow[4 * k];
            ai = dot4(xv, wi[k], ai);
            ag = dot4(xv, wg[k], ag);
            ao = dot4(xv, wo[k], ao);
        }

        float ig = fsig(ai);
        float gg = ftanh_(ag);
        float og = fsig(ao);
        float h1 = og * ftanh_(ig * gg);

        // accumulate heads on the fly; h1 never materialized
        #pragma unroll
        for (int a = 0; a < NACT; ++a)
            pol[a] = fmaf(h1, Wp[a * HIDDEN + j], pol[a]);
        valacc = fmaf(h1, Wv[j], valacc);
    }

    // ---- write outputs: [policy (B*16) | value (B)] ----
    const int row = r0 + tid;
    float4* po = (float4*)(out + (size_t)row * NACT);
    #pragma unroll
    for (int a4 = 0; a4 < 4; ++a4) {
        float4 v;
        v.x = pol[4 * a4 + 0] + bp[4 * a4 + 0];
        v.y = pol[4 * a4 + 1] + bp[4 * a4 + 1];
        v.z = pol[4 * a4 + 2] + bp[4 * a4 + 2];
        v.w = pol[4 * a4 + 3] + bp[4 * a4 + 3];
        po[a4] = v;
    }
    out[(size_t)BATCH * NACT + row] = valacc + bv[0];
}

extern "C" void kernel_launch(void* const* d_in, const int* in_sizes, int n_in,
                              void* d_out, int out_size)
{
    (void)in_sizes; (void)n_in; (void)out_size;
    const float* x    = (const float*)d_in[0];
    const float* Wih0 = (const float*)d_in[1];
    /* d_in[2] = Whh0: unused (h=0) */
    const float* bih0 = (const float*)d_in[3];
    const float* bhh0 = (const float*)d_in[4];
    const float* Wih1 = (const float*)d_in[5];
    /* d_in[6] = Whh1: unused (h=0) */
    const float* bih1 = (const float*)d_in[7];
    const float* bhh1 = (const float*)d_in[8];
    const float* Wp   = (const float*)d_in[9];
    const float* bp   = (const float*)d_in[10];
    const float* Wv   = (const float*)d_in[11];
    const float* bv   = (const float*)d_in[12];
    float* out = (float*)d_out;

    size_t shmem = (size_t)(TILE_B * XS_STRIDE + TILE_B * H0_STRIDE) * sizeof(float); // 100 KB
    cudaFuncSetAttribute(lstm_policy_fused,
                         cudaFuncAttributeMaxDynamicSharedMemorySize, (int)shmem);

    lstm_policy_fused<<<BATCH / TILE_B, THREADS, shmem>>>(
        x, Wih0, bih0, bhh0, Wih1, bih1, bhh1, Wp, bp, Wv, bv, out);
}

// round 6
// speedup vs baseline: 4.3831x; 4.3831x over previous
#include <cuda_runtime.h>
#include <cuda_bf16.h>
#include <cstdint>
#include <cstddef>

#define BATCH  65536
#define TILE_M 128
#define AS     528            // smem row stride bytes (33*16 -> conflict-free ldmatrix)
#define SM_A   0
#define SM_B   67584          // 128 rows * 528
#define SMEM_TOTAL 135168

// ---------------- pre-packed B fragments (per-lane mma layout) ----------------
// entry index: ((ntile*KT2 + ktile)*32 + lane)*2 + reg
// kt < KT2/2 : hi-half weights, kt >= KT2/2 : lo-half weights (K-concat split)
__device__ uint32_t g_B0[48 * 8 * 32 * 2];     // layer0: 48 ntiles, KT2=8  (K'=128)
__device__ uint32_t g_B1[48 * 16 * 32 * 2];    // layer1: 48 ntiles, KT2=16 (K'=256)
__device__ uint32_t g_B2[3 * 16 * 32 * 2];     // heads : 3 ntiles (N=24), KT2=16
__device__ float g_b0[384], g_b1[384];         // folded biases, gate-major (i,g,o)

__device__ __forceinline__ void wpack(float w0, float w1, uint32_t& hi, uint32_t& lo) {
    __nv_bfloat16 h0 = __float2bfloat16(w0), h1 = __float2bfloat16(w1);
    float f0 = __bfloat162float(h0), f1 = __bfloat162float(h1);
    __nv_bfloat16 l0 = __float2bfloat16(w0 - f0), l1 = __float2bfloat16(w1 - f1);
    hi = (uint32_t)*(uint16_t*)&h0 | ((uint32_t)*(uint16_t*)&h1 << 16);
    lo = (uint32_t)*(uint16_t*)&l0 | ((uint32_t)*(uint16_t*)&l1 << 16);
}

__global__ void prep_kernel(const float* __restrict__ Wih0,
                            const float* __restrict__ bih0, const float* __restrict__ bhh0,
                            const float* __restrict__ Wih1,
                            const float* __restrict__ bih1, const float* __restrict__ bhh1,
                            const float* __restrict__ Wp,   const float* __restrict__ Wv)
{
    int t = blockIdx.x * blockDim.x + threadIdx.x;
    int NT = gridDim.x * blockDim.x;
    // gate source row bases in the [4H, K] weights: i=0, g=2H=256, o=3H=384 (f dead: h=c=0)

    // ---- layer0: K=64, KT2=8 ----
    for (int e = t; e < 48 * 8 * 32; e += NT) {
        int lane = e & 31, kt = (e >> 5) & 7, nt = e >> 8;
        int col = (nt << 3) + (lane >> 2);          // 0..383
        int gate = col >> 7, j = col & 127;
        int srcR = ((gate == 1) ? 256 : (gate == 2) ? 384 : 0) + j;
        const float* Wr = Wih0 + (size_t)srcR * 64;
        int ks = (kt & 3) * 16 + ((lane & 3) << 1);
        bool lo_half = kt >= 4;
        #pragma unroll
        for (int r = 0; r < 2; r++) {
            int k = ks + (r << 3);
            uint32_t hi, lo; wpack(Wr[k], Wr[k + 1], hi, lo);
            g_B0[(((nt << 3) + kt) * 32 + lane) * 2 + r] = lo_half ? lo : hi;
        }
    }
    // ---- layer1: K=128, KT2=16 ----
    for (int e = t; e < 48 * 16 * 32; e += NT) {
        int lane = e & 31, kt = (e >> 5) & 15, nt = e >> 9;
        int col = (nt << 3) + (lane >> 2);
        int gate = col >> 7, j = col & 127;
        int srcR = ((gate == 1) ? 256 : (gate == 2) ? 384 : 0) + j;
        const float* Wr = Wih1 + (size_t)srcR * 128;
        int ks = (kt & 7) * 16 + ((lane & 3) << 1);
        bool lo_half = kt >= 8;
        #pragma unroll
        for (int r = 0; r < 2; r++) {
            int k = ks + (r << 3);
            uint32_t hi, lo; wpack(Wr[k], Wr[k + 1], hi, lo);
            g_B1[(((nt << 4) + kt) * 32 + lane) * 2 + r] = lo_half ? lo : hi;
        }
    }
    // ---- heads: rows 0-15 = Wp, 16 = Wv, 17-23 = 0 ----
    for (int e = t; e < 3 * 16 * 32; e += NT) {
        int lane = e & 31, kt = (e >> 5) & 15, nt = e >> 9;
        int col = (nt << 3) + (lane >> 2);
        int ks = (kt & 7) * 16 + ((lane & 3) << 1);
        bool lo_half = kt >= 8;
        #pragma unroll
        for (int r = 0; r < 2; r++) {
            int k = ks + (r << 3);
            float w0 = (col < 16) ? Wp[(size_t)col * 128 + k]     : ((col == 16) ? Wv[k]     : 0.0f);
            float w1 = (col < 16) ? Wp[(size_t)col * 128 + k + 1] : ((col == 16) ? Wv[k + 1] : 0.0f);
            uint32_t hi, lo; wpack(w0, w1, hi, lo);
            g_B2[(((nt << 4) + kt) * 32 + lane) * 2 + r] = lo_half ? lo : hi;
        }
    }
    for (int i = t; i < 384; i += NT) {
        int gate = i >> 7, j = i & 127;
        int R = ((gate == 1) ? 256 : (gate == 2) ? 384 : 0) + j;
        g_b0[i] = bih0[R] + bhh0[R];
        g_b1[i] = bih1[R] + bhh1[R];
    }
}

// ---------------- mma / ldmatrix helpers ----------------
__device__ __forceinline__ uint32_t smem_u32(const void* p) {
    uint32_t a;
    asm("{ .reg .u64 t; cvta.to.shared.u64 t, %1; cvt.u32.u64 %0, t; }" : "=r"(a) : "l"(p));
    return a;
}
__device__ __forceinline__ void ldmx4(uint32_t* r, uint32_t a) {
    asm volatile("ldmatrix.sync.aligned.m8n8.x4.shared.b16 {%0,%1,%2,%3}, [%4];"
                 : "=r"(r[0]), "=r"(r[1]), "=r"(r[2]), "=r"(r[3]) : "r"(a));
}
__device__ __forceinline__ void mma16816(float* c, const uint32_t* a, uint32_t b0, uint32_t b1) {
    asm volatile("mma.sync.aligned.m16n8k16.row.col.f32.bf16.bf16.f32 "
                 "{%0,%1,%2,%3}, {%4,%5,%6,%7}, {%8,%9}, {%0,%1,%2,%3};"
                 : "+f"(c[0]), "+f"(c[1]), "+f"(c[2]), "+f"(c[3])
                 : "r"(a[0]), "r"(a[1]), "r"(a[2]), "r"(a[3]), "r"(b0), "r"(b1));
}
__device__ __forceinline__ float fsig(float z)   { return __fdividef(1.0f, 1.0f + __expf(-z)); }
__device__ __forceinline__ float ftanh_(float z) { return 2.0f * fsig(2.0f * z) - 1.0f; }

// ---------------- one LSTM layer: GEMM + activation, warp-local ----------------
template <int KT2>
__device__ __forceinline__ void gemm_layer(char* smem, uint32_t sbase,
                                           int aOff, int hOff,
                                           const uint32_t* __restrict__ Bf,
                                           const float* __restrict__ bias,
                                           int m0, int lane)
{
    for (int jc = 0; jc < 4; jc++) {
        float acc[2][3][4][4];
        #pragma unroll
        for (int z = 0; z < 96; z++) ((float*)acc)[z] = 0.0f;

        for (int kt = 0; kt < KT2; kt++) {
            uint32_t Ah[2][4];
            #pragma unroll
            for (int mt = 0; mt < 2; mt++) {
                uint32_t a = sbase + (uint32_t)aOff
                           + (uint32_t)(m0 + mt * 16 + (lane & 15)) * AS
                           + (uint32_t)(kt * 32 + (lane >> 4) * 16);
                ldmx4(Ah[mt], a);
            }
            #pragma unroll
            for (int g = 0; g < 3; g++)
                #pragma unroll
                for (int nt = 0; nt < 4; nt++) {
                    int ntg = (g << 4) + (jc << 2) + nt;
                    uint2 b = *(const uint2*)&Bf[((ntg * KT2 + kt) * 32 + lane) * 2];
                    #pragma unroll
                    for (int mt = 0; mt < 2; mt++)
                        mma16816(acc[mt][g][nt], Ah[mt], b.x, b.y);
                }
        }
        // epilogue: gates -> h, split h into bf16 hi|lo (K-concat layout) in smem
        #pragma unroll
        for (int mt = 0; mt < 2; mt++)
            #pragma unroll
            for (int nt = 0; nt < 4; nt++)
                #pragma unroll
                for (int i2 = 0; i2 < 2; i2++) {
                    int jb = (jc << 5) + (nt << 3) + ((lane & 3) << 1);
                    float h[2];
                    #pragma unroll
                    for (int q = 0; q < 2; q++) {
                        int j = jb + q;
                        float ai = acc[mt][0][nt][2 * i2 + q] + __ldg(bias + j);
                        float ag = acc[mt][1][nt][2 * i2 + q] + __ldg(bias + 128 + j);
                        float ao = acc[mt][2][nt][2 * i2 + q] + __ldg(bias + 256 + j);
                        float ig = fsig(ai), gg = ftanh_(ag), og = fsig(ao);
                        h[q] = og * ftanh_(ig * gg);   // f*c = 0
                    }
                    uint32_t hp, lp; wpack(h[0], h[1], hp, lp);
                    int row = m0 + mt * 16 + (lane >> 2) + (i2 << 3);
                    char* p = smem + hOff + row * AS + jb * 2;
                    *(uint32_t*)p         = hp;    // hi: k-cols 0..127
                    *(uint32_t*)(p + 256) = lp;    // lo: k-cols 128..255
                }
    }
}

__global__ void __launch_bounds__(128)
lstm_mma_kernel(const float* __restrict__ x,
                const float* __restrict__ bp, const float* __restrict__ bv,
                float* __restrict__ out)
{
    extern __shared__ char smem[];
    uint32_t sbase = smem_u32(smem);
    int lane = threadIdx.x & 31;
    int m0 = (threadIdx.x >> 5) << 5;      // warp-owned 32 rows
    int r0 = blockIdx.x * TILE_M;

    // ---- stage x (hi cols 0..63 -> bytes 0..127, lo -> bytes 128..255) into buf A ----
    {
        const float4* xg = (const float4*)(x + (size_t)(r0 + m0) * 64);
        for (int it = lane; it < 32 * 16; it += 32) {
            int r = it >> 4, c4 = it & 15;
            float4 v = xg[r * 16 + c4];
            uint32_t h0, l0, h1, l1;
            wpack(v.x, v.y, h0, l0);
            wpack(v.z, v.w, h1, l1);
            char* p = smem + SM_A + (m0 + r) * AS + (c4 << 3);
            *(uint32_t*)p         = h0;  *(uint32_t*)(p + 4)   = h1;
            *(uint32_t*)(p + 128) = l0;  *(uint32_t*)(p + 132) = l1;
        }
    }
    __syncwarp();

    gemm_layer<8>(smem, sbase, SM_A, SM_B, g_B0, g_b0, m0, lane);   // layer0: A=x, out h0 -> buf B
    __syncwarp();
    gemm_layer<16>(smem, sbase, SM_B, SM_A, g_B1, g_b1, m0, lane);  // layer1: A=h0, out h1 -> buf A (x dead)
    __syncwarp();

    // ---- heads: h1 @ [Wp;Wv]^T, N=24 (cols 17..23 are zero-weight) ----
    {
        float acc[2][3][4];
        #pragma unroll
        for (int z = 0; z < 24; z++) ((float*)acc)[z] = 0.0f;
        for (int kt = 0; kt < 16; kt++) {
            uint32_t Ah[2][4];
            #pragma unroll
            for (int mt = 0; mt < 2; mt++) {
                uint32_t a = sbase + SM_A
                           + (uint32_t)(m0 + mt * 16 + (lane & 15)) * AS
                           + (uint32_t)(kt * 32 + (lane >> 4) * 16);
                ldmx4(Ah[mt], a);
            }
            #pragma unroll
            for (int nt = 0; nt < 3; nt++) {
                uint2 b = *(const uint2*)&g_B2[(((nt << 4) + kt) * 32 + lane) * 2];
                #pragma unroll
                for (int mt = 0; mt < 2; mt++)
                    mma16816(acc[mt][nt], Ah[mt], b.x, b.y);
            }
        }
        float bv0 = __ldg(bv);
        #pragma unroll
        for (int mt = 0; mt < 2; mt++)
            #pragma unroll
            for (int i2 = 0; i2 < 2; i2++) {
                int row = r0 + m0 + mt * 16 + (lane >> 2) + (i2 << 3);
                #pragma unroll
                for (int nt = 0; nt < 2; nt++) {
                    int j0 = (nt << 3) + ((lane & 3) << 1);
                    float2 v;
                    v.x = acc[mt][nt][2 * i2]     + __ldg(bp + j0);
                    v.y = acc[mt][nt][2 * i2 + 1] + __ldg(bp + j0 + 1);
                    *(float2*)(out + (size_t)row * 16 + j0) = v;
                }
                if ((lane & 3) == 0)   // col 16 of head block = value
                    out[(size_t)BATCH * 16 + row] = acc[mt][2][2 * i2] + bv0;
            }
    }
}

extern "C" void kernel_launch(void* const* d_in, const int* in_sizes, int n_in,
                              void* d_out, int out_size)
{
    (void)in_sizes; (void)n_in; (void)out_size;
    const float* x    = (const float*)d_in[0];
    const float* Wih0 = (const float*)d_in[1];
    const float* bih0 = (const float*)d_in[3];
    const float* bhh0 = (const float*)d_in[4];
    const float* Wih1 = (const float*)d_in[5];
    const float* bih1 = (const float*)d_in[7];
    const float* bhh1 = (const float*)d_in[8];
    const float* Wp   = (const float*)d_in[9];
    const float* bp   = (const float*)d_in[10];
    const float* Wv   = (const float*)d_in[11];
    const float* bv   = (const float*)d_in[12];
    float* out = (float*)d_out;

    prep_kernel<<<64, 256>>>(Wih0, bih0, bhh0, Wih1, bih1, bhh1, Wp, Wv);

    cudaFuncSetAttribute(lstm_mma_kernel,
                         cudaFuncAttributeMaxDynamicSharedMemorySize, SMEM_TOTAL);
    lstm_mma_kernel<<<BATCH / TILE_M, 128, SMEM_TOTAL>>>(x, bp, bv, out);
}

// round 7
// speedup vs baseline: 6.2074x; 1.4162x over previous
#include <cuda_runtime.h>
#include <cuda_bf16.h>
#include <cstdint>
#include <cstddef>

#define BATCH  65536
#define TILE_M 64
#define AS     528            // smem row stride (33*16): conflict-free ldmatrix
#define SM_BUFA 0
#define SM_BUFB 33792         // 64*528
#define SM_BIAS 67584         // b0[384] f32 then b1[384] f32
#define SMEM_TOTAL 70656

// ---------------- pre-packed B fragments (per-lane mma layout, 2 sections: hi then lo) ----------------
// entry: ((ntile*KT2 + bkt)*32 + lane)*2 + reg ; bkt < KT2/2 -> hi weights, else lo
__device__ uint32_t g_B0[48 * 8 * 32 * 2];     // layer0: 48 ntiles, KT2=8  (K=64)
__device__ uint32_t g_B1[48 * 16 * 32 * 2];    // layer1: 48 ntiles, KT2=16 (K=128)
__device__ uint32_t g_B2[3 * 16 * 32 * 2];     // heads : 3 ntiles (N=24)
__device__ float g_b0[384], g_b1[384];         // folded biases, gate-major (i,g,o)

__device__ __forceinline__ void wpack(float w0, float w1, uint32_t& hi, uint32_t& lo) {
    __nv_bfloat16 h0 = __float2bfloat16(w0), h1 = __float2bfloat16(w1);
    float f0 = __bfloat162float(h0), f1 = __bfloat162float(h1);
    __nv_bfloat16 l0 = __float2bfloat16(w0 - f0), l1 = __float2bfloat16(w1 - f1);
    hi = (uint32_t)*(uint16_t*)&h0 | ((uint32_t)*(uint16_t*)&h1 << 16);
    lo = (uint32_t)*(uint16_t*)&l0 | ((uint32_t)*(uint16_t*)&l1 << 16);
}

__global__ void prep_kernel(const float* __restrict__ Wih0,
                            const float* __restrict__ bih0, const float* __restrict__ bhh0,
                            const float* __restrict__ Wih1,
                            const float* __restrict__ bih1, const float* __restrict__ bhh1,
                            const float* __restrict__ Wp,   const float* __restrict__ Wv)
{
    int t = blockIdx.x * blockDim.x + threadIdx.x;
    int NT = gridDim.x * blockDim.x;
    // gate source row bases: i=0, g=256, o=384 (f dead: h=c=0)
    for (int e = t; e < 48 * 8 * 32; e += NT) {          // layer0
        int lane = e & 31, kt = (e >> 5) & 7, nt = e >> 8;
        int col = (nt << 3) + (lane >> 2);
        int gate = col >> 7, j = col & 127;
        int srcR = ((gate == 1) ? 256 : (gate == 2) ? 384 : 0) + j;
        const float* Wr = Wih0 + (size_t)srcR * 64;
        int ks = (kt & 3) * 16 + ((lane & 3) << 1);
        bool lo_half = kt >= 4;
        #pragma unroll
        for (int r = 0; r < 2; r++) {
            int k = ks + (r << 3);
            uint32_t hi, lo; wpack(Wr[k], Wr[k + 1], hi, lo);
            g_B0[(((nt << 3) + kt) * 32 + lane) * 2 + r] = lo_half ? lo : hi;
        }
    }
    for (int e = t; e < 48 * 16 * 32; e += NT) {         // layer1
        int lane = e & 31, kt = (e >> 5) & 15, nt = e >> 9;
        int col = (nt << 3) + (lane >> 2);
        int gate = col >> 7, j = col & 127;
        int srcR = ((gate == 1) ? 256 : (gate == 2) ? 384 : 0) + j;
        const float* Wr = Wih1 + (size_t)srcR * 128;
        int ks = (kt & 7) * 16 + ((lane & 3) << 1);
        bool lo_half = kt >= 8;
        #pragma unroll
        for (int r = 0; r < 2; r++) {
            int k = ks + (r << 3);
            uint32_t hi, lo; wpack(Wr[k], Wr[k + 1], hi, lo);
            g_B1[(((nt << 4) + kt) * 32 + lane) * 2 + r] = lo_half ? lo : hi;
        }
    }
    for (int e = t; e < 3 * 16 * 32; e += NT) {          // heads: rows 0-15 Wp, 16 Wv, 17-23 zero
        int lane = e & 31, kt = (e >> 5) & 15, nt = e >> 9;
        int col = (nt << 3) + (lane >> 2);
        int ks = (kt & 7) * 16 + ((lane & 3) << 1);
        bool lo_half = kt >= 8;
        #pragma unroll
        for (int r = 0; r < 2; r++) {
            int k = ks + (r << 3);
            float w0 = (col < 16) ? Wp[(size_t)col * 128 + k]     : ((col == 16) ? Wv[k]     : 0.0f);
            float w1 = (col < 16) ? Wp[(size_t)col * 128 + k + 1] : ((col == 16) ? Wv[k + 1] : 0.0f);
            uint32_t hi, lo; wpack(w0, w1, hi, lo);
            g_B2[(((nt << 4) + kt) * 32 + lane) * 2 + r] = lo_half ? lo : hi;
        }
    }
    for (int i = t; i < 384; i += NT) {
        int gate = i >> 7, j = i & 127;
        int R = ((gate == 1) ? 256 : (gate == 2) ? 384 : 0) + j;
        g_b0[i] = bih0[R] + bhh0[R];
        g_b1[i] = bih1[R] + bhh1[R];
    }
}

// ---------------- mma helpers ----------------
__device__ __forceinline__ uint32_t smem_u32(const void* p) {
    uint32_t a;
    asm("{ .reg .u64 t; cvta.to.shared.u64 t, %1; cvt.u32.u64 %0, t; }" : "=r"(a) : "l"(p));
    return a;
}
__device__ __forceinline__ void ldmx4(uint32_t* r, uint32_t a) {
    asm volatile("ldmatrix.sync.aligned.m8n8.x4.shared.b16 {%0,%1,%2,%3}, [%4];"
                 : "=r"(r[0]), "=r"(r[1]), "=r"(r[2]), "=r"(r[3]) : "r"(a));
}
__device__ __forceinline__ void mma16816(float* c, const uint32_t* a, uint32_t b0, uint32_t b1) {
    asm volatile("mma.sync.aligned.m16n8k16.row.col.f32.bf16.bf16.f32 "
                 "{%0,%1,%2,%3}, {%4,%5,%6,%7}, {%8,%9}, {%0,%1,%2,%3};"
                 : "+f"(c[0]), "+f"(c[1]), "+f"(c[2]), "+f"(c[3])
                 : "r"(a[0]), "r"(a[1]), "r"(a[2]), "r"(a[3]), "r"(b0), "r"(b1));
}
__device__ __forceinline__ float fsig(float z)   { return __fdividef(1.0f, 1.0f + __expf(-z)); }
__device__ __forceinline__ float ftanh_(float z) { return 2.0f * fsig(2.0f * z) - 1.0f; }

// ---------------- one LSTM layer: 3-section GEMM + activation ----------------
// KTB = k16-tiles per section (4 for K=64, 8 for K=128). kt runs 0..3*KTB-1:
//   S1: A_hi*B_hi   S2: A_lo*B_hi   S3: A_hi*B_lo
template <int KTB>
__device__ __forceinline__ void gemm_layer(char* smem, uint32_t sbase,
                                           int aOff, int hOff,
                                           const uint32_t* __restrict__ Bf,
                                           const float* __restrict__ bias,  // smem ptr
                                           int m0, int lane, int jhalf)
{
    #pragma unroll
    for (int jci = 0; jci < 2; jci++) {
        int jc = 2 * jhalf + jci;
        float acc[2][3][4][4];
        #pragma unroll
        for (int z = 0; z < 96; z++) ((float*)acc)[z] = 0.0f;

        #pragma unroll 4
        for (int kt = 0; kt < 3 * KTB; kt++) {
            int akt = (kt < 2 * KTB) ? kt : kt - 2 * KTB;
            int bkt = (kt < KTB) ? kt : kt - KTB;
            uint32_t Ah[2][4];
            #pragma unroll
            for (int mt = 0; mt < 2; mt++) {
                uint32_t a = sbase + (uint32_t)aOff
                           + (uint32_t)(m0 + mt * 16 + (lane & 15)) * AS
                           + (uint32_t)(akt * 32 + (lane >> 4) * 16);
                ldmx4(Ah[mt], a);
            }
            #pragma unroll
            for (int g = 0; g < 3; g++)
                #pragma unroll
                for (int nt = 0; nt < 4; nt++) {
                    int ntg = (g << 4) + (jc << 2) + nt;
                    uint2 b = *(const uint2*)&Bf[((ntg * 2 * KTB + bkt) * 32 + lane) * 2];
                    #pragma unroll
                    for (int mt = 0; mt < 2; mt++)
                        mma16816(acc[mt][g][nt], Ah[mt], b.x, b.y);
                }
        }
        // epilogue: gates -> h, split h into bf16 hi (bytes 0..255) | lo (bytes 256..511)
        #pragma unroll
        for (int mt = 0; mt < 2; mt++)
            #pragma unroll
            for (int nt = 0; nt < 4; nt++)
                #pragma unroll
                for (int i2 = 0; i2 < 2; i2++) {
                    int jb = (jc << 5) + (nt << 3) + ((lane & 3) << 1);
                    float h[2];
                    #pragma unroll
                    for (int q = 0; q < 2; q++) {
                        int j = jb + q;
                        float ai = acc[mt][0][nt][2 * i2 + q] + bias[j];
                        float ag = acc[mt][1][nt][2 * i2 + q] + bias[128 + j];
                        float ao = acc[mt][2][nt][2 * i2 + q] + bias[256 + j];
                        float ig = fsig(ai), gg = ftanh_(ag), og = fsig(ao);
                        h[q] = og * ftanh_(ig * gg);   // f*c = 0
                    }
                    uint32_t hp, lp; wpack(h[0], h[1], hp, lp);
                    int row = m0 + mt * 16 + (lane >> 2) + (i2 << 3);
                    char* p = smem + hOff + row * AS + jb * 2;
                    *(uint32_t*)p         = hp;
                    *(uint32_t*)(p + 256) = lp;
                }
    }
}

__global__ void __launch_bounds__(128, 3)
lstm_mma_kernel(const float* __restrict__ x,
                const float* __restrict__ bp, const float* __restrict__ bv,
                float* __restrict__ out)
{
    extern __shared__ char smem[];
    uint32_t sbase = smem_u32(smem);
    int tid = threadIdx.x;
    int lane = tid & 31;
    int warp = tid >> 5;
    int jhalf = warp & 1;            // which half of N-columns this warp owns
    int m0 = (warp >> 1) << 5;       // row group: warps {0,1}->rows 0-31, {2,3}->32-63
    int r0 = blockIdx.x * TILE_M;

    // ---- stage biases to smem ----
    float* bias_s = (float*)(smem + SM_BIAS);
    for (int i = tid; i < 384; i += 128) { bias_s[i] = g_b0[i]; bias_s[384 + i] = g_b1[i]; }

    // ---- stage x into bufA: hi bytes 0..127, lo bytes 128..255 per row ----
    {
        const float4* xg = (const float4*)(x + (size_t)r0 * 64);
        for (int it = tid; it < 64 * 16; it += 128) {
            int r = it >> 4, c4 = it & 15;
            float4 v = xg[r * 16 + c4];
            uint32_t h0, l0, h1, l1;
            wpack(v.x, v.y, h0, l0);
            wpack(v.z, v.w, h1, l1);
            char* p = smem + SM_BUFA + r * AS + (c4 << 3);
            *(uint32_t*)p         = h0;  *(uint32_t*)(p + 4)   = h1;
            *(uint32_t*)(p + 128) = l0;  *(uint32_t*)(p + 132) = l1;
        }
    }
    __syncthreads();

    gemm_layer<4>(smem, sbase, SM_BUFA, SM_BUFB, g_B0, bias_s,       m0, lane, jhalf);  // x -> h0
    __syncthreads();
    gemm_layer<8>(smem, sbase, SM_BUFB, SM_BUFA, g_B1, bias_s + 384, m0, lane, jhalf);  // h0 -> h1
    __syncthreads();

    // ---- heads: h1 @ [Wp;Wv]^T, N=24, 3-section K. jhalf0: nt{0,2}, jhalf1: nt{1} ----
    {
        float acc[2][2][4];
        #pragma unroll
        for (int z = 0; z < 16; z++) ((float*)acc)[z] = 0.0f;
        int nt0 = jhalf ? 1 : 0;
        int nt1 = jhalf ? -1 : 2;    // second tile only for jhalf0

        #pragma unroll 4
        for (int kt = 0; kt < 24; kt++) {
            int akt = (kt < 16) ? kt : kt - 16;
            int bkt = (kt < 8) ? kt : kt - 8;
            uint32_t Ah[2][4];
            #pragma unroll
            for (int mt = 0; mt < 2; mt++) {
                uint32_t a = sbase + SM_BUFA
                           + (uint32_t)(m0 + mt * 16 + (lane & 15)) * AS
                           + (uint32_t)(akt * 32 + (lane >> 4) * 16);
                ldmx4(Ah[mt], a);
            }
            {
                uint2 b = *(const uint2*)&g_B2[(((nt0 << 4) + bkt) * 32 + lane) * 2];
                #pragma unroll
                for (int mt = 0; mt < 2; mt++) mma16816(acc[mt][0], Ah[mt], b.x, b.y);
            }
            if (nt1 >= 0) {
                uint2 b = *(const uint2*)&g_B2[(((nt1 << 4) + bkt) * 32 + lane) * 2];
                #pragma unroll
                for (int mt = 0; mt < 2; mt++) mma16816(acc[mt][1], Ah[mt], b.x, b.y);
            }
        }
        float bv0 = __ldg(bv);
        #pragma unroll
        for (int mt = 0; mt < 2; mt++)
            #pragma unroll
            for (int i2 = 0; i2 < 2; i2++) {
                int row = r0 + m0 + mt * 16 + (lane >> 2) + (i2 << 3);
                {   // policy tile nt0 (cols nt0*8 .. nt0*8+7)
                    int j0 = (nt0 << 3) + ((lane & 3) << 1);
                    float2 v;
                    v.x = acc[mt][0][2 * i2]     + __ldg(bp + j0);
                    v.y = acc[mt][0][2 * i2 + 1] + __ldg(bp + j0 + 1);
                    *(float2*)(out + (size_t)row * 16 + j0) = v;
                }
                if (nt1 >= 0 && (lane & 3) == 0)   // value = col 16 (tile 2, first col pair, q=0)
                    out[(size_t)BATCH * 16 + row] = acc[mt][1][2 * i2] + bv0;
            }
    }
}

extern "C" void kernel_launch(void* const* d_in, const int* in_sizes, int n_in,
                              void* d_out, int out_size)
{
    (void)in_sizes; (void)n_in; (void)out_size;
    const float* x    = (const float*)d_in[0];
    const float* Wih0 = (const float*)d_in[1];
    const float* bih0 = (const float*)d_in[3];
    const float* bhh0 = (const float*)d_in[4];
    const float* Wih1 = (const float*)d_in[5];
    const float* bih1 = (const float*)d_in[7];
    const float* bhh1 = (const float*)d_in[8];
    const float* Wp   = (const float*)d_in[9];
    const float* bp   = (const float*)d_in[10];
    const float* Wv   = (const float*)d_in[11];
    const float* bv   = (const float*)d_in[12];
    float* out = (float*)d_out;

    prep_kernel<<<64, 256>>>(Wih0, bih0, bhh0, Wih1, bih1, bhh1, Wp, Wv);

    cudaFuncSetAttribute(lstm_mma_kernel,
                         cudaFuncAttributeMaxDynamicSharedMemorySize, SMEM_TOTAL);
    lstm_mma_kernel<<<BATCH / TILE_M, 128, SMEM_TOTAL>>>(x, bp, bv, out);
}

// round 8
// speedup vs baseline: 12.5311x; 2.0187x over previous
#include <cuda_runtime.h>
#include <cuda_fp16.h>
#include <cstdint>
#include <cstddef>

#define BATCH  65536
#define TILE_M 64
#define AS     272            // smem row stride (17*16): conflict-free ldmatrix phases
#define SM_BUFA 0
#define SM_BUFB 17408         // 64*272
#define SM_BIAS 34816         // b0[384] f32 then b1[384] f32
#define SMEM_TOTAL 37888

// ---------------- pre-packed fp16 B fragments (per-lane mma layout) ----------------
// entry: ((ntile*KT + kt)*32 + lane)*2 + reg
__device__ uint32_t g_B0[48 * 4 * 32 * 2];     // layer0: 48 ntiles, KT=4 (K=64)
__device__ uint32_t g_B1[48 * 8 * 32 * 2];     // layer1: 48 ntiles, KT=8 (K=128)
__device__ uint32_t g_B2[3 * 8 * 32 * 2];      // heads : 3 ntiles (N=24)
__device__ float g_b0[384], g_b1[384];         // folded biases, gate-major (i,g,o)

__device__ __forceinline__ uint32_t hpack(float w0, float w1) {
    __half2 h = __floats2half2_rn(w0, w1);
    return *(uint32_t*)&h;
}

__global__ void prep_kernel(const float* __restrict__ Wih0,
                            const float* __restrict__ bih0, const float* __restrict__ bhh0,
                            const float* __restrict__ Wih1,
                            const float* __restrict__ bih1, const float* __restrict__ bhh1,
                            const float* __restrict__ Wp,   const float* __restrict__ Wv)
{
    int t = blockIdx.x * blockDim.x + threadIdx.x;
    int NT = gridDim.x * blockDim.x;
    // gate source row bases: i=0, g=256, o=384 (f dead: h=c=0)
    for (int e = t; e < 48 * 4 * 32; e += NT) {          // layer0, K=64
        int lane = e & 31, kt = (e >> 5) & 3, nt = e >> 7;
        int col = (nt << 3) + (lane >> 2);
        int gate = col >> 7, j = col & 127;
        int srcR = ((gate == 1) ? 256 : (gate == 2) ? 384 : 0) + j;
        const float* Wr = Wih0 + (size_t)srcR * 64;
        int ks = kt * 16 + ((lane & 3) << 1);
        #pragma unroll
        for (int r = 0; r < 2; r++) {
            int k = ks + (r << 3);
            g_B0[(((nt << 2) + kt) * 32 + lane) * 2 + r] = hpack(Wr[k], Wr[k + 1]);
        }
    }
    for (int e = t; e < 48 * 8 * 32; e += NT) {          // layer1, K=128
        int lane = e & 31, kt = (e >> 5) & 7, nt = e >> 8;
        int col = (nt << 3) + (lane >> 2);
        int gate = col >> 7, j = col & 127;
        int srcR = ((gate == 1) ? 256 : (gate == 2) ? 384 : 0) + j;
        const float* Wr = Wih1 + (size_t)srcR * 128;
        int ks = kt * 16 + ((lane & 3) << 1);
        #pragma unroll
        for (int r = 0; r < 2; r++) {
            int k = ks + (r << 3);
            g_B1[(((nt << 3) + kt) * 32 + lane) * 2 + r] = hpack(Wr[k], Wr[k + 1]);
        }
    }
    for (int e = t; e < 3 * 8 * 32; e += NT) {           // heads: rows 0-15 Wp, 16 Wv, 17-23 zero
        int lane = e & 31, kt = (e >> 5) & 7, nt = e >> 8;
        int col = (nt << 3) + (lane >> 2);
        int ks = kt * 16 + ((lane & 3) << 1);
        #pragma unroll
        for (int r = 0; r < 2; r++) {
            int k = ks + (r << 3);
            float w0 = (col < 16) ? Wp[(size_t)col * 128 + k]     : ((col == 16) ? Wv[k]     : 0.0f);
            float w1 = (col < 16) ? Wp[(size_t)col * 128 + k + 1] : ((col == 16) ? Wv[k + 1] : 0.0f);
            g_B2[(((nt << 3) + kt) * 32 + lane) * 2 + r] = hpack(w0, w1);
        }
    }
    for (int i = t; i < 384; i += NT) {
        int gate = i >> 7, j = i & 127;
        int R = ((gate == 1) ? 256 : (gate == 2) ? 384 : 0) + j;
        g_b0[i] = bih0[R] + bhh0[R];
        g_b1[i] = bih1[R] + bhh1[R];
    }
}

// ---------------- mma helpers ----------------
__device__ __forceinline__ uint32_t smem_u32(const void* p) {
    uint32_t a;
    asm("{ .reg .u64 t; cvta.to.shared.u64 t, %1; cvt.u32.u64 %0, t; }" : "=r"(a) : "l"(p));
    return a;
}
__device__ __forceinline__ void ldmx4(uint32_t* r, uint32_t a) {
    asm volatile("ldmatrix.sync.aligned.m8n8.x4.shared.b16 {%0,%1,%2,%3}, [%4];"
                 : "=r"(r[0]), "=r"(r[1]), "=r"(r[2]), "=r"(r[3]) : "r"(a));
}
__device__ __forceinline__ void mma16816(float* c, const uint32_t* a, uint32_t b0, uint32_t b1) {
    asm volatile("mma.sync.aligned.m16n8k16.row.col.f32.f16.f16.f32 "
                 "{%0,%1,%2,%3}, {%4,%5,%6,%7}, {%8,%9}, {%0,%1,%2,%3};"
                 : "+f"(c[0]), "+f"(c[1]), "+f"(c[2]), "+f"(c[3])
                 : "r"(a[0]), "r"(a[1]), "r"(a[2]), "r"(a[3]), "r"(b0), "r"(b1));
}
__device__ __forceinline__ float fsig(float z)   { return __fdividef(1.0f, 1.0f + __expf(-z)); }
__device__ __forceinline__ float ftanh_(float z) { return 2.0f * fsig(2.0f * z) - 1.0f; }

// ---------------- one LSTM layer: fp16 GEMM + fp32 activation ----------------
template <int KT>
__device__ __forceinline__ void gemm_layer(char* smem, uint32_t sbase,
                                           int aOff, int hOff,
                                           const uint32_t* __restrict__ Bf,
                                           const float* __restrict__ bias,  // smem ptr
                                           int m0, int lane, int jhalf)
{
    #pragma unroll
    for (int jci = 0; jci < 2; jci++) {
        int jc = 2 * jhalf + jci;
        float acc[2][3][4][4];
        #pragma unroll
        for (int z = 0; z < 96; z++) ((float*)acc)[z] = 0.0f;

        #pragma unroll
        for (int kt = 0; kt < KT; kt++) {
            uint32_t Ah[2][4];
            #pragma unroll
            for (int mt = 0; mt < 2; mt++) {
                uint32_t a = sbase + (uint32_t)aOff
                           + (uint32_t)(m0 + mt * 16 + (lane & 15)) * AS
                           + (uint32_t)(kt * 32 + (lane >> 4) * 16);
                ldmx4(Ah[mt], a);
            }
            #pragma unroll
            for (int g = 0; g < 3; g++)
                #pragma unroll
                for (int nt = 0; nt < 4; nt++) {
                    int ntg = (g << 4) + (jc << 2) + nt;
                    uint2 b = *(const uint2*)&Bf[((ntg * KT + kt) * 32 + lane) * 2];
                    #pragma unroll
                    for (int mt = 0; mt < 2; mt++)
                        mma16816(acc[mt][g][nt], Ah[mt], b.x, b.y);
                }
        }
        // epilogue: gates -> h (fp32 activations) -> fp16 into next A buffer
        #pragma unroll
        for (int mt = 0; mt < 2; mt++)
            #pragma unroll
            for (int nt = 0; nt < 4; nt++)
                #pragma unroll
                for (int i2 = 0; i2 < 2; i2++) {
                    int jb = (jc << 5) + (nt << 3) + ((lane & 3) << 1);
                    float h[2];
                    #pragma unroll
                    for (int q = 0; q < 2; q++) {
                        int j = jb + q;
                        float ai = acc[mt][0][nt][2 * i2 + q] + bias[j];
                        float ag = acc[mt][1][nt][2 * i2 + q] + bias[128 + j];
                        float ao = acc[mt][2][nt][2 * i2 + q] + bias[256 + j];
                        float ig = fsig(ai), gg = ftanh_(ag), og = fsig(ao);
                        h[q] = og * ftanh_(ig * gg);   // f*c = 0
                    }
                    int row = m0 + mt * 16 + (lane >> 2) + (i2 << 3);
                    *(uint32_t*)(smem + hOff + row * AS + jb * 2) = hpack(h[0], h[1]);
                }
    }
}

__global__ void __launch_bounds__(128, 3)
lstm_mma_kernel(const float* __restrict__ x,
                const float* __restrict__ bp, const float* __restrict__ bv,
                float* __restrict__ out)
{
    extern __shared__ char smem[];
    uint32_t sbase = smem_u32(smem);
    int tid = threadIdx.x;
    int lane = tid & 31;
    int warp = tid >> 5;
    int jhalf = warp & 1;            // N-column half owned by this warp
    int m0 = (warp >> 1) << 5;       // row group
    int r0 = blockIdx.x * TILE_M;

    // ---- stage biases ----
    float* bias_s = (float*)(smem + SM_BIAS);
    for (int i = tid; i < 384; i += 128) { bias_s[i] = g_b0[i]; bias_s[384 + i] = g_b1[i]; }

    // ---- stage x as fp16 into bufA (128B per row) ----
    {
        const float4* xg = (const float4*)(x + (size_t)r0 * 64);
        for (int it = tid; it < 64 * 16; it += 128) {
            int r = it >> 4, c4 = it & 15;
            float4 v = xg[r * 16 + c4];
            char* p = smem + SM_BUFA + r * AS + (c4 << 3);
            *(uint32_t*)p       = hpack(v.x, v.y);
            *(uint32_t*)(p + 4) = hpack(v.z, v.w);
        }
    }
    __syncthreads();

    gemm_layer<4>(smem, sbase, SM_BUFA, SM_BUFB, g_B0, bias_s,       m0, lane, jhalf);  // x -> h0
    __syncthreads();
    gemm_layer<8>(smem, sbase, SM_BUFB, SM_BUFA, g_B1, bias_s + 384, m0, lane, jhalf);  // h0 -> h1
    __syncthreads();

    // ---- heads: h1 @ [Wp;Wv]^T, N=24. jhalf0: nt{0,2}, jhalf1: nt{1} ----
    {
        float acc[2][2][4];
        #pragma unroll
        for (int z = 0; z < 16; z++) ((float*)acc)[z] = 0.0f;
        int nt0 = jhalf ? 1 : 0;
        int nt1 = jhalf ? -1 : 2;    // second tile only for jhalf0

        #pragma unroll
        for (int kt = 0; kt < 8; kt++) {
            uint32_t Ah[2][4];
            #pragma unroll
            for (int mt = 0; mt < 2; mt++) {
                uint32_t a = sbase + SM_BUFA
                           + (uint32_t)(m0 + mt * 16 + (lane & 15)) * AS
                           + (uint32_t)(kt * 32 + (lane >> 4) * 16);
                ldmx4(Ah[mt], a);
            }
            {
                uint2 b = *(const uint2*)&g_B2[(((nt0 << 3) + kt) * 32 + lane) * 2];
                #pragma unroll
                for (int mt = 0; mt < 2; mt++) mma16816(acc[mt][0], Ah[mt], b.x, b.y);
            }
            if (nt1 >= 0) {
                uint2 b = *(const uint2*)&g_B2[(((nt1 << 3) + kt) * 32 + lane) * 2];
                #pragma unroll
                for (int mt = 0; mt < 2; mt++) mma16816(acc[mt][1], Ah[mt], b.x, b.y);
            }
        }
        float bv0 = __ldg(bv);
        #pragma unroll
        for (int mt = 0; mt < 2; mt++)
            #pragma unroll
            for (int i2 = 0; i2 < 2; i2++) {
                int row = r0 + m0 + mt * 16 + (lane >> 2) + (i2 << 3);
                {   // policy tile nt0 (cols nt0*8 .. nt0*8+7)
                    int j0 = (nt0 << 3) + ((lane & 3) << 1);
                    float2 v;
                    v.x = acc[mt][0][2 * i2]     + __ldg(bp + j0);
                    v.y = acc[mt][0][2 * i2 + 1] + __ldg(bp + j0 + 1);
                    *(float2*)(out + (size_t)row * 16 + j0) = v;
                }
                if (nt1 >= 0 && (lane & 3) == 0)   // value = col 16
                    out[(size_t)BATCH * 16 + row] = acc[mt][1][2 * i2] + bv0;
            }
    }
}

extern "C" void kernel_launch(void* const* d_in, const int* in_sizes, int n_in,
                              void* d_out, int out_size)
{
    (void)in_sizes; (void)n_in; (void)out_size;
    const float* x    = (const float*)d_in[0];
    const float* Wih0 = (const float*)d_in[1];
    const float* bih0 = (const float*)d_in[3];
    const float* bhh0 = (const float*)d_in[4];
    const float* Wih1 = (const float*)d_in[5];
    const float* bih1 = (const float*)d_in[7];
    const float* bhh1 = (const float*)d_in[8];
    const float* Wp   = (const float*)d_in[9];
    const float* bp   = (const float*)d_in[10];
    const float* Wv   = (const float*)d_in[11];
    const float* bv   = (const float*)d_in[12];
    float* out = (float*)d_out;

    prep_kernel<<<64, 256>>>(Wih0, bih0, bhh0, Wih1, bih1, bhh1, Wp, Wv);

    cudaFuncSetAttribute(lstm_mma_kernel,
                         cudaFuncAttributeMaxDynamicSharedMemorySize, SMEM_TOTAL);
    lstm_mma_kernel<<<BATCH / TILE_M, 128, SMEM_TOTAL>>>(x, bp, bv, out);
}

// round 10
// speedup vs baseline: 15.2849x; 1.2198x over previous
#include <cuda_runtime.h>
#include <cuda_fp16.h>
#include <cstdint>
#include <cstddef>

#define BATCH  65536
#define TILE_M 64
#define AS     272            // smem row stride (17*16): conflict-free ldmatrix phases
#define SM_BUFA 0
#define SM_BUFB 17408         // 64*272
#define SM_BIAS 34816         // b0[384] f32 then b1[384] f32
#define SMEM_TOTAL 37888

// ---------------- pre-packed fp16 B fragments (per-lane mma layout) ----------------
__device__ uint32_t g_B0[48 * 4 * 32 * 2];     // layer0: 48 ntiles, KT=4 (K=64)
__device__ uint32_t g_B1[48 * 8 * 32 * 2];     // layer1: 48 ntiles, KT=8 (K=128)
__device__ uint32_t g_B2[3 * 8 * 32 * 2];      // heads : 3 ntiles (N=24)
__device__ float g_b0[384], g_b1[384];         // folded biases, gate-major (i,g,o)

__device__ __forceinline__ uint32_t hpack(float w0, float w1) {
    __half2 h = __floats2half2_rn(w0, w1);
    return *(uint32_t*)&h;
}

__global__ void prep_kernel(const float* __restrict__ Wih0,
                            const float* __restrict__ bih0, const float* __restrict__ bhh0,
                            const float* __restrict__ Wih1,
                            const float* __restrict__ bih1, const float* __restrict__ bhh1,
                            const float* __restrict__ Wp,   const float* __restrict__ Wv)
{
    int t = blockIdx.x * blockDim.x + threadIdx.x;
    int NT = gridDim.x * blockDim.x;
    // gate source row bases: i=0, g=256, o=384 (f dead: h=c=0)
    for (int e = t; e < 48 * 4 * 32; e += NT) {          // layer0, K=64
        int lane = e & 31, kt = (e >> 5) & 3, nt = e >> 7;
        int col = (nt << 3) + (lane >> 2);
        int gate = col >> 7, j = col & 127;
        int srcR = ((gate == 1) ? 256 : (gate == 2) ? 384 : 0) + j;
        const float* Wr = Wih0 + (size_t)srcR * 64;
        int ks = kt * 16 + ((lane & 3) << 1);
        #pragma unroll
        for (int r = 0; r < 2; r++) {
            int k = ks + (r << 3);
            g_B0[(((nt << 2) + kt) * 32 + lane) * 2 + r] = hpack(Wr[k], Wr[k + 1]);
        }
    }
    for (int e = t; e < 48 * 8 * 32; e += NT) {          // layer1, K=128
        int lane = e & 31, kt = (e >> 5) & 7, nt = e >> 8;
        int col = (nt << 3) + (lane >> 2);
        int gate = col >> 7, j = col & 127;
        int srcR = ((gate == 1) ? 256 : (gate == 2) ? 384 : 0) + j;
        const float* Wr = Wih1 + (size_t)srcR * 128;
        int ks = kt * 16 + ((lane & 3) << 1);
        #pragma unroll
        for (int r = 0; r < 2; r++) {
            int k = ks + (r << 3);
            g_B1[(((nt << 3) + kt) * 32 + lane) * 2 + r] = hpack(Wr[k], Wr[k + 1]);
        }
    }
    for (int e = t; e < 3 * 8 * 32; e += NT) {           // heads: rows 0-15 Wp, 16 Wv, 17-23 zero
        int lane = e & 31, kt = (e >> 5) & 7, nt = e >> 8;
        int col = (nt << 3) + (lane >> 2);
        int ks = kt * 16 + ((lane & 3) << 1);
        #pragma unroll
        for (int r = 0; r < 2; r++) {
            int k = ks + (r << 3);
            float w0 = (col < 16) ? Wp[(size_t)col * 128 + k]     : ((col == 16) ? Wv[k]     : 0.0f);
            float w1 = (col < 16) ? Wp[(size_t)col * 128 + k + 1] : ((col == 16) ? Wv[k + 1] : 0.0f);
            g_B2[(((nt << 3) + kt) * 32 + lane) * 2 + r] = hpack(w0, w1);
        }
    }
    for (int i = t; i < 384; i += NT) {
        int gate = i >> 7, j = i & 127;
        int R = ((gate == 1) ? 256 : (gate == 2) ? 384 : 0) + j;
        g_b0[i] = bih0[R] + bhh0[R];
        g_b1[i] = bih1[R] + bhh1[R];
    }
}

// ---------------- mma / activation helpers ----------------
__device__ __forceinline__ uint32_t smem_u32(const void* p) {
    uint32_t a;
    asm("{ .reg .u64 t; cvta.to.shared.u64 t, %1; cvt.u32.u64 %0, t; }" : "=r"(a) : "l"(p));
    return a;
}
__device__ __forceinline__ void ldmx4(uint32_t* r, uint32_t a) {
    asm volatile("ldmatrix.sync.aligned.m8n8.x4.shared.b16 {%0,%1,%2,%3}, [%4];"
                 : "=r"(r[0]), "=r"(r[1]), "=r"(r[2]), "=r"(r[3]) : "r"(a));
}
__device__ __forceinline__ void mma16816(float* c, const uint32_t* a, uint32_t b0, uint32_t b1) {
    asm volatile("mma.sync.aligned.m16n8k16.row.col.f32.f16.f16.f32 "
                 "{%0,%1,%2,%3}, {%4,%5,%6,%7}, {%8,%9}, {%0,%1,%2,%3};"
                 : "+f"(c[0]), "+f"(c[1]), "+f"(c[2]), "+f"(c[3])
                 : "r"(a[0]), "r"(a[1]), "r"(a[2]), "r"(a[3]), "r"(b0), "r"(b1));
}
__device__ __forceinline__ __half2 htanh2(__half2 v) {
    uint32_t r, xin = *(uint32_t*)&v;
    asm("tanh.approx.f16x2 %0, %1;" : "=r"(r) : "r"(xin));
    return *(__half2*)&r;
}

// ---------------- one LSTM layer: fp16 GEMM + f16x2 activation ----------------
// Warp owns 16 rows (m0) x 64 cols (jhalf). h = sigma(ai)*tanh? -> f16x2 math:
//   sigma(z) = 0.5 + 0.5*tanh(z/2); tanh via tanh.approx.f16x2; f-gate & c are zero.
template <int KT>
__device__ __forceinline__ void gemm_layer(char* smem, uint32_t sbase,
                                           int aOff, int hOff,
                                           const uint32_t* __restrict__ Bf,
                                           const float* __restrict__ bias,  // smem ptr
                                           int m0, int lane, int jhalf)
{
    const __half2 H05 = __floats2half2_rn(0.5f, 0.5f);
    #pragma unroll
    for (int jci = 0; jci < 2; jci++) {
        int jc = 2 * jhalf + jci;
        float acc[3][4][4];
        #pragma unroll
        for (int z = 0; z < 48; z++) ((float*)acc)[z] = 0.0f;

        #pragma unroll
        for (int kt = 0; kt < KT; kt++) {
            uint32_t Ah[4];
            uint32_t a = sbase + (uint32_t)aOff
                       + (uint32_t)(m0 + (lane & 15)) * AS
                       + (uint32_t)(kt * 32 + (lane >> 4) * 16);
            ldmx4(Ah, a);
            #pragma unroll
            for (int g = 0; g < 3; g++)
                #pragma unroll
                for (int nt = 0; nt < 4; nt++) {
                    int ntg = (g << 4) + (jc << 2) + nt;
                    uint2 b = *(const uint2*)&Bf[((ntg * KT + kt) * 32 + lane) * 2];
                    mma16816(acc[g][nt], Ah, b.x, b.y);
                }
        }
        // epilogue: f16x2 activations, 4 MUFU per col-pair
        #pragma unroll
        for (int nt = 0; nt < 4; nt++)
            #pragma unroll
            for (int i2 = 0; i2 < 2; i2++) {
                int jb = (jc << 5) + (nt << 3) + ((lane & 3) << 1);
                float ai0 = acc[0][nt][2 * i2]     + bias[jb];
                float ai1 = acc[0][nt][2 * i2 + 1] + bias[jb + 1];
                float ag0 = acc[1][nt][2 * i2]     + bias[128 + jb];
                float ag1 = acc[1][nt][2 * i2 + 1] + bias[128 + jb + 1];
                float ao0 = acc[2][nt][2 * i2]     + bias[256 + jb];
                float ao1 = acc[2][nt][2 * i2 + 1] + bias[256 + jb + 1];
                __half2 si = __hfma2(htanh2(__floats2half2_rn(0.5f * ai0, 0.5f * ai1)), H05, H05);
                __half2 gg = htanh2(__floats2half2_rn(ag0, ag1));
                __half2 so = __hfma2(htanh2(__floats2half2_rn(0.5f * ao0, 0.5f * ao1)), H05, H05);
                __half2 tc = htanh2(__hmul2(si, gg));      // c = i*g (f*c = 0)
                __half2 h2 = __hmul2(so, tc);
                int row = m0 + (lane >> 2) + (i2 << 3);
                *(uint32_t*)(smem + hOff + row * AS + jb * 2) = *(uint32_t*)&h2;
            }
    }
}

__global__ void __launch_bounds__(256, 2)
lstm_mma_kernel(const float* __restrict__ x,
                const float* __restrict__ bp, const float* __restrict__ bv,
                float* __restrict__ out)
{
    extern __shared__ char smem[];
    uint32_t sbase = smem_u32(smem);
    int tid = threadIdx.x;
    int lane = tid & 31;
    int warp = tid >> 5;
    int jhalf = warp & 1;            // N-column half owned by this warp
    int m0 = (warp >> 1) << 4;       // 16-row group
    int r0 = blockIdx.x * TILE_M;

    // ---- stage biases ----
    float* bias_s = (float*)(smem + SM_BIAS);
    for (int i = tid; i < 384; i += 256) { bias_s[i] = g_b0[i]; bias_s[384 + i] = g_b1[i]; }

    // ---- stage x as fp16 into bufA (128B per row) ----
    {
        const float4* xg = (const float4*)(x + (size_t)r0 * 64);
        for (int it = tid; it < 64 * 16; it += 256) {
            int r = it >> 4, c4 = it & 15;
            float4 v = xg[r * 16 + c4];
            char* p = smem + SM_BUFA + r * AS + (c4 << 3);
            *(uint32_t*)p       = hpack(v.x, v.y);
            *(uint32_t*)(p + 4) = hpack(v.z, v.w);
        }
    }
    __syncthreads();

    gemm_layer<4>(smem, sbase, SM_BUFA, SM_BUFB, g_B0, bias_s,       m0, lane, jhalf);  // x -> h0
    __syncthreads();
    gemm_layer<8>(smem, sbase, SM_BUFB, SM_BUFA, g_B1, bias_s + 384, m0, lane, jhalf);  // h0 -> h1
    __syncthreads();

    // ---- heads: h1 @ [Wp;Wv]^T, N=24. jhalf0: nt{0,2}, jhalf1: nt{1} ----
    {
        float acc[2][4];
        #pragma unroll
        for (int z = 0; z < 8; z++) ((float*)acc)[z] = 0.0f;
        int nt0 = jhalf ? 1 : 0;
        int nt1 = jhalf ? -1 : 2;    // second tile only for jhalf0

        #pragma unroll
        for (int kt = 0; kt < 8; kt++) {
            uint32_t Ah[4];
            uint32_t a = sbase + SM_BUFA
                       + (uint32_t)(m0 + (lane & 15)) * AS
                       + (uint32_t)(kt * 32 + (lane >> 4) * 16);
            ldmx4(Ah, a);
            {
                uint2 b = *(const uint2*)&g_B2[(((nt0 << 3) + kt) * 32 + lane) * 2];
                mma16816(acc[0], Ah, b.x, b.y);
            }
            if (nt1 >= 0) {
                uint2 b = *(const uint2*)&g_B2[(((nt1 << 3) + kt) * 32 + lane) * 2];
                mma16816(acc[1], Ah, b.x, b.y);
            }
        }
        float bv0 = __ldg(bv);
        #pragma unroll
        for (int i2 = 0; i2 < 2; i2++) {
            int row = r0 + m0 + (lane >> 2) + (i2 << 3);
            {   // policy tile nt0 (cols nt0*8 .. nt0*8+7)
                int j0 = (nt0 << 3) + ((lane & 3) << 1);
                float2 v;
                v.x = acc[0][2 * i2]     + __ldg(bp + j0);
                v.y = acc[0][2 * i2 + 1] + __ldg(bp + j0 + 1);
                *(float2*)(out + (size_t)row * 16 + j0) = v;
            }
            if (nt1 >= 0 && (lane & 3) == 0)   // value = col 16
                out[(size_t)BATCH * 16 + row] = acc[1][2 * i2] + bv0;
        }
    }
}

extern "C" void kernel_launch(void* const* d_in, const int* in_sizes, int n_in,
                              void* d_out, int out_size)
{
    (void)in_sizes; (void)n_in; (void)out_size;
    const float* x    = (const float*)d_in[0];
    const float* Wih0 = (const float*)d_in[1];
    const float* bih0 = (const float*)d_in[3];
    const float* bhh0 = (const float*)d_in[4];
    const float* Wih1 = (const float*)d_in[5];
    const float* bih1 = (const float*)d_in[7];
    const float* bhh1 = (const float*)d_in[8];
    const float* Wp   = (const float*)d_in[9];
    const float* bp   = (const float*)d_in[10];
    const float* Wv   = (const float*)d_in[11];
    const float* bv   = (const float*)d_in[12];
    float* out = (float*)d_out;

    prep_kernel<<<64, 256>>>(Wih0, bih0, bhh0, Wih1, bih1, bhh1, Wp, Wv);

    cudaFuncSetAttribute(lstm_mma_kernel,
                         cudaFuncAttributeMaxDynamicSharedMemorySize, SMEM_TOTAL);
    lstm_mma_kernel<<<BATCH / TILE_M, 256, SMEM_TOTAL>>>(x, bp, bv, out);
}